// round 11
// baseline (speedup 1.0000x reference)
#include <cuda_runtime.h>
#include <math.h>

// Problem constants
#define BATCH 256
#define SEQ   200
#define D     64
#define MSLOT 50
#define NUMQ  1000
#define BN    (BATCH*SEQ)        // 51200 rows
#define R1    128                // rows per CTA in k1/k3
#define NC1   (BN/R1)            // 400 CTAs
#define CH    25                 // k2 chunk length (steps)
#define NCH   (SEQ/CH)           // 8 chunks

// Scratch (device globals; runtime allocation is forbidden)
__device__ float g_w[BN*64];     // softmax weights, padded 50->64 (pad zeroed)
__device__ float g_e[BN*64];     // erase gate
__device__ float g_a[BN*64];     // add vector
__device__ float g_k[BN*64];     // gathered k embedding
__device__ float g_read[BN*64];  // read vectors from the scan

__device__ __forceinline__ float fsig(float x)  { return 1.f / (1.f + __expf(-x)); }
__device__ __forceinline__ float ftanh_(float x){ return 1.f - 2.f / (__expf(2.f*x) + 1.f); }

__device__ __forceinline__ void fma8x4(const float* xs, float4 w, float4* A) {
#pragma unroll
    for (int u = 0; u < 8; u++) {
        A[u].x = fmaf(xs[u], w.x, A[u].x);
        A[u].y = fmaf(xs[u], w.y, A[u].y);
        A[u].z = fmaf(xs[u], w.z, A[u].z);
        A[u].w = fmaf(xs[u], w.w, A[u].w);
    }
}

// ---------------------------------------------------------------------------
// Kernel 1 (R5 version): gathers + e/a heads + softmax.
// ---------------------------------------------------------------------------
__global__ __launch_bounds__(256, 3)
void k1_heads(const int* __restrict__ q, const int* __restrict__ r,
              const float* __restrict__ k_emb, const float* __restrict__ v_emb,
              const float* __restrict__ Mk,
              const float* __restrict__ eW, const float* __restrict__ eb,
              const float* __restrict__ aW, const float* __restrict__ ab)
{
    extern __shared__ float sm[];
    float* vT = sm;                 // 64 x 132
    float* W1 = sm + 8448;          // 64 x 68
    float* W2 = sm + 8448 + 4352;   // 64 x 68
    __shared__ int qI[R1], xI[R1];

    const int tid = threadIdx.x;
    const int r0  = blockIdx.x * R1;

    if (tid < R1) {
        int qq = q[r0+tid], rr = r[r0+tid];
        qI[tid] = qq;
        xI[tid] = qq + NUMQ*rr;
    }
    __syncthreads();

    {
        const float4* v4 = reinterpret_cast<const float4*>(v_emb);
        for (int idx = tid; idx < 2048; idx += 256) {
            int i = idx & 127, c4 = idx >> 7;
            float4 v = v4[(size_t)xI[i]*16 + c4];
            int cb = c4*4;
            vT[(cb+0)*132+i] = v.x; vT[(cb+1)*132+i] = v.y;
            vT[(cb+2)*132+i] = v.z; vT[(cb+3)*132+i] = v.w;
        }
        for (int idx = tid; idx < 4096; idx += 256) {
            int c = idx & 63, j = idx >> 6;
            W1[c*68+j] = eW[idx];
            W2[c*68+j] = aW[idx];
        }
    }
    __syncthreads();

    const int tx = tid & 15, ty = tid >> 4;
    const int i0 = ty*8, j0 = tx*4;

    // ---- e pass ----
    {
        float4 acc[8];
#pragma unroll
        for (int u = 0; u < 8; u++) acc[u] = make_float4(0,0,0,0);
#pragma unroll 4
        for (int c = 0; c < 64; c++) {
            float4 x0 = *reinterpret_cast<float4*>(&vT[c*132 + i0]);
            float4 x1 = *reinterpret_cast<float4*>(&vT[c*132 + i0 + 4]);
            float4 we = *reinterpret_cast<float4*>(&W1[c*68 + j0]);
            float xs[8] = {x0.x,x0.y,x0.z,x0.w,x1.x,x1.y,x1.z,x1.w};
            fma8x4(xs, we, acc);
        }
        float4 be = *reinterpret_cast<const float4*>(&eb[j0]);
        float4* gE4 = reinterpret_cast<float4*>(g_e);
#pragma unroll
        for (int u = 0; u < 8; u++) {
            float4 o;
            o.x = fsig(acc[u].x + be.x); o.y = fsig(acc[u].y + be.y);
            o.z = fsig(acc[u].z + be.z); o.w = fsig(acc[u].w + be.w);
            gE4[(size_t)(r0 + i0 + u)*16 + tx] = o;
        }
    }

    // ---- a pass ----
    {
        float4 acc[8];
#pragma unroll
        for (int u = 0; u < 8; u++) acc[u] = make_float4(0,0,0,0);
#pragma unroll 4
        for (int c = 0; c < 64; c++) {
            float4 x0 = *reinterpret_cast<float4*>(&vT[c*132 + i0]);
            float4 x1 = *reinterpret_cast<float4*>(&vT[c*132 + i0 + 4]);
            float4 wa = *reinterpret_cast<float4*>(&W2[c*68 + j0]);
            float xs[8] = {x0.x,x0.y,x0.z,x0.w,x1.x,x1.y,x1.z,x1.w};
            fma8x4(xs, wa, acc);
        }
        float4 ba = *reinterpret_cast<const float4*>(&ab[j0]);
        float4* gA4 = reinterpret_cast<float4*>(g_a);
#pragma unroll
        for (int u = 0; u < 8; u++) {
            float4 p;
            p.x = ftanh_(acc[u].x + ba.x); p.y = ftanh_(acc[u].y + ba.y);
            p.z = ftanh_(acc[u].z + ba.z); p.w = ftanh_(acc[u].w + ba.w);
            gA4[(size_t)(r0 + i0 + u)*16 + tx] = p;
        }
    }
    __syncthreads();

    {
        const float4* k4 = reinterpret_cast<const float4*>(k_emb);
        float4* gK4 = reinterpret_cast<float4*>(g_k);
        for (int idx = tid; idx < 2048; idx += 256) {
            int i = idx & 127, c4 = idx >> 7;
            float4 kv = k4[(size_t)qI[i]*16 + c4];
            gK4[(size_t)(r0+i)*16 + c4] = kv;
            int cb = c4*4;
            vT[(cb+0)*132+i] = kv.x; vT[(cb+1)*132+i] = kv.y;
            vT[(cb+2)*132+i] = kv.z; vT[(cb+3)*132+i] = kv.w;
        }
        for (int idx = tid; idx < 4096; idx += 256) {
            int c = idx & 63, j = idx >> 6;
            W1[c*68+j] = (j < MSLOT) ? Mk[j*64 + c] : 0.f;
        }
    }
    __syncthreads();

    float4 aL[8];
#pragma unroll
    for (int u = 0; u < 8; u++) aL[u] = make_float4(0,0,0,0);
#pragma unroll 4
    for (int c = 0; c < 64; c++) {
        float4 x0 = *reinterpret_cast<float4*>(&vT[c*132 + i0]);
        float4 x1 = *reinterpret_cast<float4*>(&vT[c*132 + i0 + 4]);
        float4 wm = *reinterpret_cast<float4*>(&W1[c*68 + j0]);
        float xs[8] = {x0.x,x0.y,x0.z,x0.w,x1.x,x1.y,x1.z,x1.w};
        fma8x4(xs, wm, aL);
    }
    __syncthreads();

    float* lg = vT;
#pragma unroll
    for (int u = 0; u < 8; u++) {
        int base = (i0+u)*66 + j0;
        lg[base+0] = aL[u].x; lg[base+1] = aL[u].y;
        lg[base+2] = aL[u].z; lg[base+3] = aL[u].w;
    }
    __syncthreads();

    if (tid < R1) {
        float mx = -1e30f;
        for (int j = 0; j < MSLOT; j++) mx = fmaxf(mx, lg[tid*66 + j]);
        float s = 0.f;
        for (int j = 0; j < MSLOT; j++) {
            float ev = __expf(lg[tid*66 + j] - mx);
            lg[tid*66 + j] = ev;
            s += ev;
        }
        float inv = 1.f / s;
        for (int j = 0; j < MSLOT; j++) lg[tid*66 + j] *= inv;
        for (int j = MSLOT; j < 64; j++) lg[tid*66 + j] = 0.f;
    }
    __syncthreads();

    for (int idx = tid; idx < 8192; idx += 256) {
        int c = idx & 63, i = idx >> 6;
        g_w[(size_t)(r0 + i)*64 + c] = lg[i*66 + c];
    }
}

// ---------------------------------------------------------------------------
// Kernel 2: TWO batches per CTA. 128 CTAs x 640 threads -> exactly one CTA
// per SM (no 2-vs-1 CTA imbalance), two concurrent store streams per SM.
//   tid   0-255 : store path, batch 2b   (c4=tid&15, g=(tid&255)>>4)
//   tid 256-511 : store path, batch 2b+1
//   tid 512-575 : read path,  batch 2b   (one column per thread)
//   tid 576-639 : read path,  batch 2b+1
// Loader split: tid<320 stages batch 2b's chunks, tid>=320 stages batch 2b+1.
// dyn smem = 2 batches x 2 phases x 4800 floats = 76800 B.
// ---------------------------------------------------------------------------
__global__ __launch_bounds__(640)
void k2_scan(const float* __restrict__ Mv0, float* __restrict__ out)
{
    extern __shared__ float sb[];   // [batch][phase][4800]

    const int tid = threadIdx.x;
    const int b0  = blockIdx.x * 2;

    // ---- loader role (every thread) ----
    const int lb   = (tid >= 320);
    const int ltid = tid - 320*lb;
    const int lrow0 = (b0 + lb) * SEQ;
    float* sbL = sb + lb*9600;

    const float4* gw4 = reinterpret_cast<const float4*>(g_w);
    const float4* ge4 = reinterpret_cast<const float4*>(g_e);
    const float4* ga4 = reinterpret_cast<const float4*>(g_a);

    float4 regs[4];
    int   ridx[4];
#pragma unroll
    for (int i = 0; i < 4; i++) ridx[i] = ltid + i*320;

    // load + commit chunk 0 of this loader's batch
#pragma unroll
    for (int i = 0; i < 4; i++) {
        int idx = ridx[i];
        if (idx < CH*48) {
            int st = idx / 48, part = idx % 48;
            size_t rbase = (size_t)(lrow0 + st) * 16;
            regs[i] = (part < 16) ? __ldg(&gw4[rbase + part])
                    : (part < 32) ? __ldg(&ge4[rbase + part - 16])
                                  : __ldg(&ga4[rbase + part - 32]);
        }
    }
#pragma unroll
    for (int i = 0; i < 4; i++) {
        int idx = ridx[i];
        if (idx < CH*48) {
            int st = idx / 48, part = idx % 48;
            *reinterpret_cast<float4*>(&sbL[st*192 + part*4]) = regs[i];
        }
    }

    // ---- compute roles ----
    const int isStore = (tid < 512);
    const int sbatch  = isStore ? (tid >> 8) : ((tid - 512) >> 6);
    const int stid    = tid & 255;          // store-local id
    const int c4 = stid & 15;
    const int g  = stid >> 4;
    const int ns = (g < 2) ? 4 : 3;
    const int cc = (tid - 512) & 63;        // read-path column
    const int crow0 = (b0 + sbatch) * SEQ;

    float4* outMv = reinterpret_cast<float4*>(out) + (BN/4)
                  + (size_t)(b0 + sbatch) * (SEQ+1) * 800;

    float4 mv[4];
    float  colv[MSLOT];

    if (isStore) {
        const float4* m04 = reinterpret_cast<const float4*>(Mv0);
#pragma unroll
        for (int jj = 0; jj < 4; jj++) if (jj < ns) {
            int m = jj*16 + g;
            float4 v = m04[m*16 + c4];
            mv[jj] = v;
            outMv[m*16 + c4] = v;
        }
    } else {
#pragma unroll
        for (int m = 0; m < MSLOT; m++) colv[m] = __ldg(&Mv0[m*64 + cc]);
    }
    __syncthreads();

    for (int ch = 0; ch < NCH; ch++) {
        const int p = ch & 1;
        const float* sbc = sb + sbatch*9600 + p*4800;   // compute buffer

        // issue next chunk's loads for this loader's batch
        if (ch + 1 < NCH) {
#pragma unroll
            for (int i = 0; i < 4; i++) {
                int idx = ridx[i];
                if (idx < CH*48) {
                    int st = idx / 48, part = idx % 48;
                    size_t rbase = (size_t)(lrow0 + (ch+1)*CH + st) * 16;
                    regs[i] = (part < 16) ? __ldg(&gw4[rbase + part])
                            : (part < 32) ? __ldg(&ge4[rbase + part - 16])
                                          : __ldg(&ga4[rbase + part - 32]);
                }
            }
        }

        if (isStore) {
            // ------- store/update path -------
            for (int st = 0; st < CH; st++) {
                const float* bw = &sbc[st*192];
                float4 e4 = *reinterpret_cast<const float4*>(&bw[64  + c4*4]);
                float4 a4 = *reinterpret_cast<const float4*>(&bw[128 + c4*4]);
                float4* os = outMv + (size_t)(ch*CH + st + 1) * 800;
#pragma unroll
                for (int jj = 0; jj < 4; jj++) if (jj < ns) {
                    float w = bw[jj*16 + g];
                    float4 m = mv[jj];
                    m.x = fmaf(w, a4.x, fmaf(-m.x, w*e4.x, m.x));
                    m.y = fmaf(w, a4.y, fmaf(-m.y, w*e4.y, m.y));
                    m.z = fmaf(w, a4.z, fmaf(-m.z, w*e4.z, m.z));
                    m.w = fmaf(w, a4.w, fmaf(-m.w, w*e4.w, m.w));
                    mv[jj] = m;
                    __stcs(&os[(jj*16 + g)*16 + c4], m);
                }
            }
        } else {
            // ------- read path (one column per thread) -------
            for (int st = 0; st < CH; st++) {
                const float* bw = &sbc[st*192];
                float ce = bw[64 + cc];
                float ca = bw[128 + cc];
                float rd = 0.f;
#pragma unroll
                for (int m = 0; m < MSLOT; m++) {
                    float wm = bw[m];
                    rd = fmaf(wm, colv[m], rd);
                    colv[m] = fmaf(wm, ca, fmaf(-colv[m], wm*ce, colv[m]));
                }
                g_read[(size_t)(crow0 + ch*CH + st)*64 + cc] = rd;
            }
        }

        // commit next chunk to the alternate phase of this loader's batch
        if (ch + 1 < NCH) {
            float* sbn = sbL + (1-p)*4800;
#pragma unroll
            for (int i = 0; i < 4; i++) {
                int idx = ridx[i];
                if (idx < CH*48) {
                    int st = idx / 48, part = idx % 48;
                    *reinterpret_cast<float4*>(&sbn[st*192 + part*4]) = regs[i];
                }
            }
        }
        __syncthreads();
    }
}

// ---------------------------------------------------------------------------
// Kernel 3 (half-K version, 33.4us measured).
// ---------------------------------------------------------------------------
__global__ __launch_bounds__(256, 3)
void k3_out(const float* __restrict__ fW, const float* __restrict__ fb,
            const float* __restrict__ pW, const float* __restrict__ pb,
            float* __restrict__ out)
{
    extern __shared__ float sm[];
    float* inT = sm;            // 64 x 132 (half of K) ; reused as f (128x66)
    float* WtF = sm + 8448;     // 64 x 68
    __shared__ float pWs[64];

    const int tid = threadIdx.x;
    const int r0  = blockIdx.x * R1;
    const int tx = tid & 15, ty = tid >> 4;
    const int i0 = ty*8, j0 = tx*4;

    if (tid < 64) pWs[tid] = pW[tid];

    float4 acc[8];
#pragma unroll
    for (int u = 0; u < 8; u++) acc[u] = make_float4(0,0,0,0);

    const float4* rd4 = reinterpret_cast<const float4*>(g_read);
    const float4* kg4 = reinterpret_cast<const float4*>(g_k);

    for (int h = 0; h < 2; h++) {
        if (h) __syncthreads();
        const float4* src = (h == 0) ? rd4 : kg4;
        for (int idx = tid; idx < 2048; idx += 256) {
            int i = idx & 127, c4 = idx >> 7;
            float4 v = src[(size_t)(r0+i)*16 + c4];
            int cb = c4*4;
            inT[(cb+0)*132+i] = v.x; inT[(cb+1)*132+i] = v.y;
            inT[(cb+2)*132+i] = v.z; inT[(cb+3)*132+i] = v.w;
        }
        for (int idx = tid; idx < 4096; idx += 256) {
            int cc = idx & 63, j = idx >> 6;
            WtF[cc*68 + j] = fW[j*128 + h*64 + cc];
        }
        __syncthreads();
#pragma unroll 4
        for (int c = 0; c < 64; c++) {
            float4 x0 = *reinterpret_cast<float4*>(&inT[c*132 + i0]);
            float4 x1 = *reinterpret_cast<float4*>(&inT[c*132 + i0 + 4]);
            float4 w  = *reinterpret_cast<float4*>(&WtF[c*68 + j0]);
            float xs[8] = {x0.x,x0.y,x0.z,x0.w,x1.x,x1.y,x1.z,x1.w};
            fma8x4(xs, w, acc);
        }
    }
    float4 b4 = *reinterpret_cast<const float4*>(&fb[j0]);
    __syncthreads();

    float* fS = inT;
#pragma unroll
    for (int u = 0; u < 8; u++) {
        int base = (i0+u)*66 + j0;
        fS[base+0] = ftanh_(acc[u].x + b4.x);
        fS[base+1] = ftanh_(acc[u].y + b4.y);
        fS[base+2] = ftanh_(acc[u].z + b4.z);
        fS[base+3] = ftanh_(acc[u].w + b4.w);
    }
    __syncthreads();

    if (tid < R1) {
        float s = pb[0];
        for (int j = 0; j < 64; j++) s = fmaf(pWs[j], fS[tid*66 + j], s);
        out[r0 + tid] = fsig(s);
    }
}

// ---------------------------------------------------------------------------
extern "C" void kernel_launch(void* const* d_in, const int* in_sizes, int n_in,
                              void* d_out, int out_size)
{
    const int*   q     = (const int*)  d_in[0];
    const int*   r     = (const int*)  d_in[1];
    const float* k_emb = (const float*)d_in[2];
    const float* v_emb = (const float*)d_in[3];
    const float* Mk    = (const float*)d_in[4];
    const float* Mv0   = (const float*)d_in[5];
    const float* eW    = (const float*)d_in[6];
    const float* eb    = (const float*)d_in[7];
    const float* aW    = (const float*)d_in[8];
    const float* ab    = (const float*)d_in[9];
    const float* fW    = (const float*)d_in[10];
    const float* fb    = (const float*)d_in[11];
    const float* pW    = (const float*)d_in[12];
    const float* pb    = (const float*)d_in[13];
    float* out = (float*)d_out;

    const int SMEM1 = 17152 * 4;             // 68608 B
    const int SMEM2 = 2 * 2 * 4800 * 4;      // 76800 B
    const int SMEM3 = (8448 + 4352) * 4;     // 51200 B
    cudaFuncSetAttribute(k1_heads, cudaFuncAttributeMaxDynamicSharedMemorySize, SMEM1);
    cudaFuncSetAttribute(k2_scan,  cudaFuncAttributeMaxDynamicSharedMemorySize, SMEM2);
    cudaFuncSetAttribute(k3_out,   cudaFuncAttributeMaxDynamicSharedMemorySize, SMEM3);

    k1_heads<<<NC1, 256, SMEM1>>>(q, r, k_emb, v_emb, Mk, eW, eb, aW, ab);
    k2_scan <<<BATCH/2, 640, SMEM2>>>(Mv0, out);
    k3_out  <<<NC1, 256, SMEM3>>>(fW, fb, pW, pb, out);
}

// round 12
// speedup vs baseline: 1.0975x; 1.0975x over previous
#include <cuda_runtime.h>
#include <math.h>

// Problem constants
#define BATCH 256
#define SEQ   200
#define D     64
#define MSLOT 50
#define NUMQ  1000
#define BN    (BATCH*SEQ)        // 51200 rows
#define R1    128                // rows per CTA in k1/k3
#define NC1   (BN/R1)            // 400 CTAs
#define CH    25                 // k2 chunk length (steps)
#define NCH   (SEQ/CH)           // 8 chunks

// Scratch (device globals; runtime allocation is forbidden)
__device__ float g_w[BN*64];     // softmax weights, padded 50->64 (pad zeroed)
__device__ float g_e[BN*64];     // erase gate
__device__ float g_a[BN*64];     // add vector
__device__ float g_k[BN*64];     // gathered k embedding
__device__ float g_read[BN*64];  // read vectors from the scan

__device__ __forceinline__ float fsig(float x)  { return 1.f / (1.f + __expf(-x)); }
__device__ __forceinline__ float ftanh_(float x){ return 1.f - 2.f / (__expf(2.f*x) + 1.f); }

__device__ __forceinline__ void fma8x4(const float* xs, float4 w, float4* A) {
#pragma unroll
    for (int u = 0; u < 8; u++) {
        A[u].x = fmaf(xs[u], w.x, A[u].x);
        A[u].y = fmaf(xs[u], w.y, A[u].y);
        A[u].z = fmaf(xs[u], w.z, A[u].z);
        A[u].w = fmaf(xs[u], w.w, A[u].w);
    }
}

// ---------------------------------------------------------------------------
// Kernel 1: single weight buffer (staged 3x) -> smem 51.2KB, 4 CTAs/SM.
// ---------------------------------------------------------------------------
__global__ __launch_bounds__(256, 4)
void k1_heads(const int* __restrict__ q, const int* __restrict__ r,
              const float* __restrict__ k_emb, const float* __restrict__ v_emb,
              const float* __restrict__ Mk,
              const float* __restrict__ eW, const float* __restrict__ eb,
              const float* __restrict__ aW, const float* __restrict__ ab)
{
    extern __shared__ float sm[];
    float* vT = sm;                 // 64 x 132
    float* W1 = sm + 8448;          // 64 x 68 (restaged per pass)
    __shared__ int qI[R1], xI[R1];

    const int tid = threadIdx.x;
    const int r0  = blockIdx.x * R1;

    if (tid < R1) {
        int qq = q[r0+tid], rr = r[r0+tid];
        qI[tid] = qq;
        xI[tid] = qq + NUMQ*rr;
    }
    __syncthreads();

    // gather v transposed + stage eW^T
    {
        const float4* v4 = reinterpret_cast<const float4*>(v_emb);
        for (int idx = tid; idx < 2048; idx += 256) {
            int i = idx & 127, c4 = idx >> 7;
            float4 v = v4[(size_t)xI[i]*16 + c4];
            int cb = c4*4;
            vT[(cb+0)*132+i] = v.x; vT[(cb+1)*132+i] = v.y;
            vT[(cb+2)*132+i] = v.z; vT[(cb+3)*132+i] = v.w;
        }
        for (int idx = tid; idx < 4096; idx += 256) {
            int c = idx & 63, j = idx >> 6;
            W1[c*68+j] = eW[idx];
        }
    }
    __syncthreads();

    const int tx = tid & 15, ty = tid >> 4;
    const int i0 = ty*8, j0 = tx*4;

    // ---- e pass ----
    {
        float4 acc[8];
#pragma unroll
        for (int u = 0; u < 8; u++) acc[u] = make_float4(0,0,0,0);
#pragma unroll 4
        for (int c = 0; c < 64; c++) {
            float4 x0 = *reinterpret_cast<float4*>(&vT[c*132 + i0]);
            float4 x1 = *reinterpret_cast<float4*>(&vT[c*132 + i0 + 4]);
            float4 we = *reinterpret_cast<float4*>(&W1[c*68 + j0]);
            float xs[8] = {x0.x,x0.y,x0.z,x0.w,x1.x,x1.y,x1.z,x1.w};
            fma8x4(xs, we, acc);
        }
        float4 be = *reinterpret_cast<const float4*>(&eb[j0]);
        float4* gE4 = reinterpret_cast<float4*>(g_e);
#pragma unroll
        for (int u = 0; u < 8; u++) {
            float4 o;
            o.x = fsig(acc[u].x + be.x); o.y = fsig(acc[u].y + be.y);
            o.z = fsig(acc[u].z + be.z); o.w = fsig(acc[u].w + be.w);
            gE4[(size_t)(r0 + i0 + u)*16 + tx] = o;
        }
    }
    __syncthreads();   // done reading eW

    // stage aW^T
    for (int idx = tid; idx < 4096; idx += 256) {
        int c = idx & 63, j = idx >> 6;
        W1[c*68+j] = aW[idx];
    }
    __syncthreads();

    // ---- a pass ----
    {
        float4 acc[8];
#pragma unroll
        for (int u = 0; u < 8; u++) acc[u] = make_float4(0,0,0,0);
#pragma unroll 4
        for (int c = 0; c < 64; c++) {
            float4 x0 = *reinterpret_cast<float4*>(&vT[c*132 + i0]);
            float4 x1 = *reinterpret_cast<float4*>(&vT[c*132 + i0 + 4]);
            float4 wa = *reinterpret_cast<float4*>(&W1[c*68 + j0]);
            float xs[8] = {x0.x,x0.y,x0.z,x0.w,x1.x,x1.y,x1.z,x1.w};
            fma8x4(xs, wa, acc);
        }
        float4 ba = *reinterpret_cast<const float4*>(&ab[j0]);
        float4* gA4 = reinterpret_cast<float4*>(g_a);
#pragma unroll
        for (int u = 0; u < 8; u++) {
            float4 p;
            p.x = ftanh_(acc[u].x + ba.x); p.y = ftanh_(acc[u].y + ba.y);
            p.z = ftanh_(acc[u].z + ba.z); p.w = ftanh_(acc[u].w + ba.w);
            gA4[(size_t)(r0 + i0 + u)*16 + tx] = p;
        }
    }
    __syncthreads();   // done reading vT(v) and aW

    // gather k (store g_k) + stage Mk^T padded
    {
        const float4* k4 = reinterpret_cast<const float4*>(k_emb);
        float4* gK4 = reinterpret_cast<float4*>(g_k);
        for (int idx = tid; idx < 2048; idx += 256) {
            int i = idx & 127, c4 = idx >> 7;
            float4 kv = k4[(size_t)qI[i]*16 + c4];
            gK4[(size_t)(r0+i)*16 + c4] = kv;
            int cb = c4*4;
            vT[(cb+0)*132+i] = kv.x; vT[(cb+1)*132+i] = kv.y;
            vT[(cb+2)*132+i] = kv.z; vT[(cb+3)*132+i] = kv.w;
        }
        for (int idx = tid; idx < 4096; idx += 256) {
            int c = idx & 63, j = idx >> 6;
            W1[c*68+j] = (j < MSLOT) ? Mk[j*64 + c] : 0.f;
        }
    }
    __syncthreads();

    // ---- logits pass ----
    float4 aL[8];
#pragma unroll
    for (int u = 0; u < 8; u++) aL[u] = make_float4(0,0,0,0);
#pragma unroll 4
    for (int c = 0; c < 64; c++) {
        float4 x0 = *reinterpret_cast<float4*>(&vT[c*132 + i0]);
        float4 x1 = *reinterpret_cast<float4*>(&vT[c*132 + i0 + 4]);
        float4 wm = *reinterpret_cast<float4*>(&W1[c*68 + j0]);
        float xs[8] = {x0.x,x0.y,x0.z,x0.w,x1.x,x1.y,x1.z,x1.w};
        fma8x4(xs, wm, aL);
    }
    __syncthreads();

    float* lg = vT;
#pragma unroll
    for (int u = 0; u < 8; u++) {
        int base = (i0+u)*66 + j0;
        lg[base+0] = aL[u].x; lg[base+1] = aL[u].y;
        lg[base+2] = aL[u].z; lg[base+3] = aL[u].w;
    }
    __syncthreads();

    if (tid < R1) {
        float mx = -1e30f;
        for (int j = 0; j < MSLOT; j++) mx = fmaxf(mx, lg[tid*66 + j]);
        float s = 0.f;
        for (int j = 0; j < MSLOT; j++) {
            float ev = __expf(lg[tid*66 + j] - mx);
            lg[tid*66 + j] = ev;
            s += ev;
        }
        float inv = 1.f / s;
        for (int j = 0; j < MSLOT; j++) lg[tid*66 + j] *= inv;
        for (int j = MSLOT; j < 64; j++) lg[tid*66 + j] = 0.f;
    }
    __syncthreads();

    for (int idx = tid; idx < 8192; idx += 256) {
        int c = idx & 63, i = idx >> 6;
        g_w[(size_t)(r0 + i)*64 + c] = lg[i*66 + c];
    }
}

// ---------------------------------------------------------------------------
// Kernel 2 (R5 exact, measured as part of the 237.7 config).
// ---------------------------------------------------------------------------
__global__ __launch_bounds__(320)
void k2_scan(const float* __restrict__ Mv0, float* __restrict__ out)
{
    __shared__ __align__(16) float sb[2][CH*192];   // 2 x 19200 B

    const int tid = threadIdx.x;
    const int b   = blockIdx.x;
    const int row0 = b * SEQ;
    float4* outMv = reinterpret_cast<float4*>(out) + (BN/4)
                  + (size_t)b * (SEQ+1) * 800;

    const float4* gw4 = reinterpret_cast<const float4*>(g_w);
    const float4* ge4 = reinterpret_cast<const float4*>(g_e);
    const float4* ga4 = reinterpret_cast<const float4*>(g_a);

    float4 regs[4];
    int   ridx[4];
#pragma unroll
    for (int i = 0; i < 4; i++) ridx[i] = tid + i*320;

    // load chunk 0
#pragma unroll
    for (int i = 0; i < 4; i++) {
        int idx = ridx[i];
        if (idx < CH*48) {
            int st = idx / 48, part = idx % 48;
            size_t rbase = (size_t)(row0 + st) * 16;
            regs[i] = (part < 16) ? __ldg(&gw4[rbase + part])
                    : (part < 32) ? __ldg(&ge4[rbase + part - 16])
                                  : __ldg(&ga4[rbase + part - 32]);
        }
    }
#pragma unroll
    for (int i = 0; i < 4; i++) {
        int idx = ridx[i];
        if (idx < CH*48) {
            int st = idx / 48, part = idx % 48;
            *reinterpret_cast<float4*>(&sb[0][st*192 + part*4]) = regs[i];
        }
    }

    const int c4 = tid & 15;
    const int g  = tid >> 4;
    const int ns = (g < 2) ? 4 : 3;
    float4 mv[4];
    float  colv[MSLOT];
    const int cc = tid - 256;

    if (tid < 256) {
        const float4* m04 = reinterpret_cast<const float4*>(Mv0);
#pragma unroll
        for (int jj = 0; jj < 4; jj++) if (jj < ns) {
            int m = jj*16 + g;
            float4 v = m04[m*16 + c4];
            mv[jj] = v;
            outMv[m*16 + c4] = v;
        }
    } else {
#pragma unroll
        for (int m = 0; m < MSLOT; m++) colv[m] = __ldg(&Mv0[m*64 + cc]);
    }
    __syncthreads();

    for (int ch = 0; ch < NCH; ch++) {
        const int p = ch & 1;
        const float* sbp = sb[p];

        if (ch + 1 < NCH) {
#pragma unroll
            for (int i = 0; i < 4; i++) {
                int idx = ridx[i];
                if (idx < CH*48) {
                    int st = idx / 48, part = idx % 48;
                    size_t rbase = (size_t)(row0 + (ch+1)*CH + st) * 16;
                    regs[i] = (part < 16) ? __ldg(&gw4[rbase + part])
                            : (part < 32) ? __ldg(&ge4[rbase + part - 16])
                                          : __ldg(&ga4[rbase + part - 32]);
                }
            }
        }

        if (tid < 256) {
            for (int st = 0; st < CH; st++) {
                const float* bw = &sbp[st*192];
                float4 e4 = *reinterpret_cast<const float4*>(&bw[64  + c4*4]);
                float4 a4 = *reinterpret_cast<const float4*>(&bw[128 + c4*4]);
                float4* os = outMv + (size_t)(ch*CH + st + 1) * 800;
#pragma unroll
                for (int jj = 0; jj < 4; jj++) if (jj < ns) {
                    float w = bw[jj*16 + g];
                    float4 m = mv[jj];
                    m.x = fmaf(w, a4.x, fmaf(-m.x, w*e4.x, m.x));
                    m.y = fmaf(w, a4.y, fmaf(-m.y, w*e4.y, m.y));
                    m.z = fmaf(w, a4.z, fmaf(-m.z, w*e4.z, m.z));
                    m.w = fmaf(w, a4.w, fmaf(-m.w, w*e4.w, m.w));
                    mv[jj] = m;
                    __stcs(&os[(jj*16 + g)*16 + c4], m);
                }
            }
        } else {
            for (int st = 0; st < CH; st++) {
                const float* bw = &sbp[st*192];
                float ce = bw[64 + cc];
                float ca = bw[128 + cc];
                float rd = 0.f;
#pragma unroll
                for (int m = 0; m < MSLOT; m++) {
                    float wm = bw[m];
                    rd = fmaf(wm, colv[m], rd);
                    colv[m] = fmaf(wm, ca, fmaf(-colv[m], wm*ce, colv[m]));
                }
                g_read[(size_t)(row0 + ch*CH + st)*64 + cc] = rd;
            }
        }

        if (ch + 1 < NCH) {
#pragma unroll
            for (int i = 0; i < 4; i++) {
                int idx = ridx[i];
                if (idx < CH*48) {
                    int st = idx / 48, part = idx % 48;
                    *reinterpret_cast<float4*>(&sb[1-p][st*192 + part*4]) = regs[i];
                }
            }
        }
        __syncthreads();
    }
}

// ---------------------------------------------------------------------------
// Kernel 3 (half-K), now 4 CTAs/SM.
// ---------------------------------------------------------------------------
__global__ __launch_bounds__(256, 4)
void k3_out(const float* __restrict__ fW, const float* __restrict__ fb,
            const float* __restrict__ pW, const float* __restrict__ pb,
            float* __restrict__ out)
{
    extern __shared__ float sm[];
    float* inT = sm;            // 64 x 132 (half of K) ; reused as f (128x66)
    float* WtF = sm + 8448;     // 64 x 68
    __shared__ float pWs[64];

    const int tid = threadIdx.x;
    const int r0  = blockIdx.x * R1;
    const int tx = tid & 15, ty = tid >> 4;
    const int i0 = ty*8, j0 = tx*4;

    if (tid < 64) pWs[tid] = pW[tid];

    float4 acc[8];
#pragma unroll
    for (int u = 0; u < 8; u++) acc[u] = make_float4(0,0,0,0);

    const float4* rd4 = reinterpret_cast<const float4*>(g_read);
    const float4* kg4 = reinterpret_cast<const float4*>(g_k);

    for (int h = 0; h < 2; h++) {
        if (h) __syncthreads();
        const float4* src = (h == 0) ? rd4 : kg4;
        for (int idx = tid; idx < 2048; idx += 256) {
            int i = idx & 127, c4 = idx >> 7;
            float4 v = src[(size_t)(r0+i)*16 + c4];
            int cb = c4*4;
            inT[(cb+0)*132+i] = v.x; inT[(cb+1)*132+i] = v.y;
            inT[(cb+2)*132+i] = v.z; inT[(cb+3)*132+i] = v.w;
        }
        for (int idx = tid; idx < 4096; idx += 256) {
            int cc = idx & 63, j = idx >> 6;
            WtF[cc*68 + j] = fW[j*128 + h*64 + cc];
        }
        __syncthreads();
#pragma unroll 4
        for (int c = 0; c < 64; c++) {
            float4 x0 = *reinterpret_cast<float4*>(&inT[c*132 + i0]);
            float4 x1 = *reinterpret_cast<float4*>(&inT[c*132 + i0 + 4]);
            float4 w  = *reinterpret_cast<float4*>(&WtF[c*68 + j0]);
            float xs[8] = {x0.x,x0.y,x0.z,x0.w,x1.x,x1.y,x1.z,x1.w};
            fma8x4(xs, w, acc);
        }
    }
    float4 b4 = *reinterpret_cast<const float4*>(&fb[j0]);
    __syncthreads();

    float* fS = inT;
#pragma unroll
    for (int u = 0; u < 8; u++) {
        int base = (i0+u)*66 + j0;
        fS[base+0] = ftanh_(acc[u].x + b4.x);
        fS[base+1] = ftanh_(acc[u].y + b4.y);
        fS[base+2] = ftanh_(acc[u].z + b4.z);
        fS[base+3] = ftanh_(acc[u].w + b4.w);
    }
    __syncthreads();

    if (tid < R1) {
        float s = pb[0];
        for (int j = 0; j < 64; j++) s = fmaf(pWs[j], fS[tid*66 + j], s);
        out[r0 + tid] = fsig(s);
    }
}

// ---------------------------------------------------------------------------
extern "C" void kernel_launch(void* const* d_in, const int* in_sizes, int n_in,
                              void* d_out, int out_size)
{
    const int*   q     = (const int*)  d_in[0];
    const int*   r     = (const int*)  d_in[1];
    const float* k_emb = (const float*)d_in[2];
    const float* v_emb = (const float*)d_in[3];
    const float* Mk    = (const float*)d_in[4];
    const float* Mv0   = (const float*)d_in[5];
    const float* eW    = (const float*)d_in[6];
    const float* eb    = (const float*)d_in[7];
    const float* aW    = (const float*)d_in[8];
    const float* ab    = (const float*)d_in[9];
    const float* fW    = (const float*)d_in[10];
    const float* fb    = (const float*)d_in[11];
    const float* pW    = (const float*)d_in[12];
    const float* pb    = (const float*)d_in[13];
    float* out = (float*)d_out;

    const int SMEM1 = (8448 + 4352) * 4;     // 51200 B
    const int SMEM3 = (8448 + 4352) * 4;     // 51200 B
    cudaFuncSetAttribute(k1_heads, cudaFuncAttributeMaxDynamicSharedMemorySize, SMEM1);
    cudaFuncSetAttribute(k3_out,   cudaFuncAttributeMaxDynamicSharedMemorySize, SMEM3);

    k1_heads<<<NC1, 256, SMEM1>>>(q, r, k_emb, v_emb, Mk, eW, eb, aW, ab);
    k2_scan <<<BATCH, 320>>>(Mv0, out);
    k3_out  <<<NC1, 256, SMEM3>>>(fW, fb, pW, pb, out);
}

// round 13
// speedup vs baseline: 1.1273x; 1.0271x over previous
#include <cuda_runtime.h>
#include <math.h>

// Problem constants
#define BATCH 256
#define SEQ   200
#define D     64
#define MSLOT 50
#define NUMQ  1000
#define BN    (BATCH*SEQ)        // 51200 rows
#define R1    128                // rows per CTA in k1/k3
#define NC1   (BN/R1)            // 400 CTAs
#define CH    25                 // k2 chunk length (steps)
#define NCH   (SEQ/CH)           // 8 chunks

// Scratch (device globals; runtime allocation is forbidden)
__device__ float g_w[BN*64];     // softmax weights, padded 50->64 (pad zeroed)
__device__ float g_e[BN*64];     // erase gate
__device__ float g_a[BN*64];     // add vector
__device__ float g_k[BN*64];     // gathered k embedding
__device__ float g_read[BN*64];  // read vectors from the scan

__device__ __forceinline__ float fsig(float x)  { return 1.f / (1.f + __expf(-x)); }
__device__ __forceinline__ float ftanh_(float x){ return 1.f - 2.f / (__expf(2.f*x) + 1.f); }

__device__ __forceinline__ void fma8x4(const float* xs, float4 w, float4* A) {
#pragma unroll
    for (int u = 0; u < 8; u++) {
        A[u].x = fmaf(xs[u], w.x, A[u].x);
        A[u].y = fmaf(xs[u], w.y, A[u].y);
        A[u].z = fmaf(xs[u], w.z, A[u].z);
        A[u].w = fmaf(xs[u], w.w, A[u].w);
    }
}

// ---------------------------------------------------------------------------
// Kernel 1 (R5 version, 58.7us measured): dual weight buffers staged upfront,
// separate e/a passes, 3 CTAs/SM, smem 68608 B.
// ---------------------------------------------------------------------------
__global__ __launch_bounds__(256, 3)
void k1_heads(const int* __restrict__ q, const int* __restrict__ r,
              const float* __restrict__ k_emb, const float* __restrict__ v_emb,
              const float* __restrict__ Mk,
              const float* __restrict__ eW, const float* __restrict__ eb,
              const float* __restrict__ aW, const float* __restrict__ ab)
{
    extern __shared__ float sm[];
    float* vT = sm;                 // 64 x 132
    float* W1 = sm + 8448;          // 64 x 68
    float* W2 = sm + 8448 + 4352;   // 64 x 68
    __shared__ int qI[R1], xI[R1];

    const int tid = threadIdx.x;
    const int r0  = blockIdx.x * R1;

    if (tid < R1) {
        int qq = q[r0+tid], rr = r[r0+tid];
        qI[tid] = qq;
        xI[tid] = qq + NUMQ*rr;
    }
    __syncthreads();

    {
        const float4* v4 = reinterpret_cast<const float4*>(v_emb);
        for (int idx = tid; idx < 2048; idx += 256) {
            int i = idx & 127, c4 = idx >> 7;
            float4 v = v4[(size_t)xI[i]*16 + c4];
            int cb = c4*4;
            vT[(cb+0)*132+i] = v.x; vT[(cb+1)*132+i] = v.y;
            vT[(cb+2)*132+i] = v.z; vT[(cb+3)*132+i] = v.w;
        }
        for (int idx = tid; idx < 4096; idx += 256) {
            int c = idx & 63, j = idx >> 6;
            W1[c*68+j] = eW[idx];
            W2[c*68+j] = aW[idx];
        }
    }
    __syncthreads();

    const int tx = tid & 15, ty = tid >> 4;
    const int i0 = ty*8, j0 = tx*4;

    // ---- e pass ----
    {
        float4 acc[8];
#pragma unroll
        for (int u = 0; u < 8; u++) acc[u] = make_float4(0,0,0,0);
#pragma unroll 4
        for (int c = 0; c < 64; c++) {
            float4 x0 = *reinterpret_cast<float4*>(&vT[c*132 + i0]);
            float4 x1 = *reinterpret_cast<float4*>(&vT[c*132 + i0 + 4]);
            float4 we = *reinterpret_cast<float4*>(&W1[c*68 + j0]);
            float xs[8] = {x0.x,x0.y,x0.z,x0.w,x1.x,x1.y,x1.z,x1.w};
            fma8x4(xs, we, acc);
        }
        float4 be = *reinterpret_cast<const float4*>(&eb[j0]);
        float4* gE4 = reinterpret_cast<float4*>(g_e);
#pragma unroll
        for (int u = 0; u < 8; u++) {
            float4 o;
            o.x = fsig(acc[u].x + be.x); o.y = fsig(acc[u].y + be.y);
            o.z = fsig(acc[u].z + be.z); o.w = fsig(acc[u].w + be.w);
            gE4[(size_t)(r0 + i0 + u)*16 + tx] = o;
        }
    }

    // ---- a pass ----
    {
        float4 acc[8];
#pragma unroll
        for (int u = 0; u < 8; u++) acc[u] = make_float4(0,0,0,0);
#pragma unroll 4
        for (int c = 0; c < 64; c++) {
            float4 x0 = *reinterpret_cast<float4*>(&vT[c*132 + i0]);
            float4 x1 = *reinterpret_cast<float4*>(&vT[c*132 + i0 + 4]);
            float4 wa = *reinterpret_cast<float4*>(&W2[c*68 + j0]);
            float xs[8] = {x0.x,x0.y,x0.z,x0.w,x1.x,x1.y,x1.z,x1.w};
            fma8x4(xs, wa, acc);
        }
        float4 ba = *reinterpret_cast<const float4*>(&ab[j0]);
        float4* gA4 = reinterpret_cast<float4*>(g_a);
#pragma unroll
        for (int u = 0; u < 8; u++) {
            float4 p;
            p.x = ftanh_(acc[u].x + ba.x); p.y = ftanh_(acc[u].y + ba.y);
            p.z = ftanh_(acc[u].z + ba.z); p.w = ftanh_(acc[u].w + ba.w);
            gA4[(size_t)(r0 + i0 + u)*16 + tx] = p;
        }
    }
    __syncthreads();

    {
        const float4* k4 = reinterpret_cast<const float4*>(k_emb);
        float4* gK4 = reinterpret_cast<float4*>(g_k);
        for (int idx = tid; idx < 2048; idx += 256) {
            int i = idx & 127, c4 = idx >> 7;
            float4 kv = k4[(size_t)qI[i]*16 + c4];
            gK4[(size_t)(r0+i)*16 + c4] = kv;
            int cb = c4*4;
            vT[(cb+0)*132+i] = kv.x; vT[(cb+1)*132+i] = kv.y;
            vT[(cb+2)*132+i] = kv.z; vT[(cb+3)*132+i] = kv.w;
        }
        for (int idx = tid; idx < 4096; idx += 256) {
            int c = idx & 63, j = idx >> 6;
            W1[c*68+j] = (j < MSLOT) ? Mk[j*64 + c] : 0.f;
        }
    }
    __syncthreads();

    float4 aL[8];
#pragma unroll
    for (int u = 0; u < 8; u++) aL[u] = make_float4(0,0,0,0);
#pragma unroll 4
    for (int c = 0; c < 64; c++) {
        float4 x0 = *reinterpret_cast<float4*>(&vT[c*132 + i0]);
        float4 x1 = *reinterpret_cast<float4*>(&vT[c*132 + i0 + 4]);
        float4 wm = *reinterpret_cast<float4*>(&W1[c*68 + j0]);
        float xs[8] = {x0.x,x0.y,x0.z,x0.w,x1.x,x1.y,x1.z,x1.w};
        fma8x4(xs, wm, aL);
    }
    __syncthreads();

    float* lg = vT;
#pragma unroll
    for (int u = 0; u < 8; u++) {
        int base = (i0+u)*66 + j0;
        lg[base+0] = aL[u].x; lg[base+1] = aL[u].y;
        lg[base+2] = aL[u].z; lg[base+3] = aL[u].w;
    }
    __syncthreads();

    if (tid < R1) {
        float mx = -1e30f;
        for (int j = 0; j < MSLOT; j++) mx = fmaxf(mx, lg[tid*66 + j]);
        float s = 0.f;
        for (int j = 0; j < MSLOT; j++) {
            float ev = __expf(lg[tid*66 + j] - mx);
            lg[tid*66 + j] = ev;
            s += ev;
        }
        float inv = 1.f / s;
        for (int j = 0; j < MSLOT; j++) lg[tid*66 + j] *= inv;
        for (int j = MSLOT; j < 64; j++) lg[tid*66 + j] = 0.f;
    }
    __syncthreads();

    for (int idx = tid; idx < 8192; idx += 256) {
        int c = idx & 63, i = idx >> 6;
        g_w[(size_t)(r0 + i)*64 + c] = lg[i*66 + c];
    }
}

// ---------------------------------------------------------------------------
// Kernel 2 (R5 exact; frozen — established HBM-write-floor bound).
// ---------------------------------------------------------------------------
__global__ __launch_bounds__(320)
void k2_scan(const float* __restrict__ Mv0, float* __restrict__ out)
{
    __shared__ __align__(16) float sb[2][CH*192];   // 2 x 19200 B

    const int tid = threadIdx.x;
    const int b   = blockIdx.x;
    const int row0 = b * SEQ;
    float4* outMv = reinterpret_cast<float4*>(out) + (BN/4)
                  + (size_t)b * (SEQ+1) * 800;

    const float4* gw4 = reinterpret_cast<const float4*>(g_w);
    const float4* ge4 = reinterpret_cast<const float4*>(g_e);
    const float4* ga4 = reinterpret_cast<const float4*>(g_a);

    float4 regs[4];
    int   ridx[4];
#pragma unroll
    for (int i = 0; i < 4; i++) ridx[i] = tid + i*320;

    // load chunk 0
#pragma unroll
    for (int i = 0; i < 4; i++) {
        int idx = ridx[i];
        if (idx < CH*48) {
            int st = idx / 48, part = idx % 48;
            size_t rbase = (size_t)(row0 + st) * 16;
            regs[i] = (part < 16) ? __ldg(&gw4[rbase + part])
                    : (part < 32) ? __ldg(&ge4[rbase + part - 16])
                                  : __ldg(&ga4[rbase + part - 32]);
        }
    }
#pragma unroll
    for (int i = 0; i < 4; i++) {
        int idx = ridx[i];
        if (idx < CH*48) {
            int st = idx / 48, part = idx % 48;
            *reinterpret_cast<float4*>(&sb[0][st*192 + part*4]) = regs[i];
        }
    }

    const int c4 = tid & 15;
    const int g  = tid >> 4;
    const int ns = (g < 2) ? 4 : 3;
    float4 mv[4];
    float  colv[MSLOT];
    const int cc = tid - 256;

    if (tid < 256) {
        const float4* m04 = reinterpret_cast<const float4*>(Mv0);
#pragma unroll
        for (int jj = 0; jj < 4; jj++) if (jj < ns) {
            int m = jj*16 + g;
            float4 v = m04[m*16 + c4];
            mv[jj] = v;
            outMv[m*16 + c4] = v;
        }
    } else {
#pragma unroll
        for (int m = 0; m < MSLOT; m++) colv[m] = __ldg(&Mv0[m*64 + cc]);
    }
    __syncthreads();

    for (int ch = 0; ch < NCH; ch++) {
        const int p = ch & 1;
        const float* sbp = sb[p];

        if (ch + 1 < NCH) {
#pragma unroll
            for (int i = 0; i < 4; i++) {
                int idx = ridx[i];
                if (idx < CH*48) {
                    int st = idx / 48, part = idx % 48;
                    size_t rbase = (size_t)(row0 + (ch+1)*CH + st) * 16;
                    regs[i] = (part < 16) ? __ldg(&gw4[rbase + part])
                            : (part < 32) ? __ldg(&ge4[rbase + part - 16])
                                          : __ldg(&ga4[rbase + part - 32]);
                }
            }
        }

        if (tid < 256) {
            for (int st = 0; st < CH; st++) {
                const float* bw = &sbp[st*192];
                float4 e4 = *reinterpret_cast<const float4*>(&bw[64  + c4*4]);
                float4 a4 = *reinterpret_cast<const float4*>(&bw[128 + c4*4]);
                float4* os = outMv + (size_t)(ch*CH + st + 1) * 800;
#pragma unroll
                for (int jj = 0; jj < 4; jj++) if (jj < ns) {
                    float w = bw[jj*16 + g];
                    float4 m = mv[jj];
                    m.x = fmaf(w, a4.x, fmaf(-m.x, w*e4.x, m.x));
                    m.y = fmaf(w, a4.y, fmaf(-m.y, w*e4.y, m.y));
                    m.z = fmaf(w, a4.z, fmaf(-m.z, w*e4.z, m.z));
                    m.w = fmaf(w, a4.w, fmaf(-m.w, w*e4.w, m.w));
                    mv[jj] = m;
                    __stcs(&os[(jj*16 + g)*16 + c4], m);
                }
            }
        } else {
            for (int st = 0; st < CH; st++) {
                const float* bw = &sbp[st*192];
                float ce = bw[64 + cc];
                float ca = bw[128 + cc];
                float rd = 0.f;
#pragma unroll
                for (int m = 0; m < MSLOT; m++) {
                    float wm = bw[m];
                    rd = fmaf(wm, colv[m], rd);
                    colv[m] = fmaf(wm, ca, fmaf(-colv[m], wm*ce, colv[m]));
                }
                g_read[(size_t)(row0 + ch*CH + st)*64 + cc] = rd;
            }
        }

        if (ch + 1 < NCH) {
#pragma unroll
            for (int i = 0; i < 4; i++) {
                int idx = ridx[i];
                if (idx < CH*48) {
                    int st = idx / 48, part = idx % 48;
                    *reinterpret_cast<float4*>(&sb[1-p][st*192 + part*4]) = regs[i];
                }
            }
        }
        __syncthreads();
    }
}

// ---------------------------------------------------------------------------
// Kernel 3 (half-K, (256,4) — best measured this round).
// ---------------------------------------------------------------------------
__global__ __launch_bounds__(256, 4)
void k3_out(const float* __restrict__ fW, const float* __restrict__ fb,
            const float* __restrict__ pW, const float* __restrict__ pb,
            float* __restrict__ out)
{
    extern __shared__ float sm[];
    float* inT = sm;            // 64 x 132 (half of K) ; reused as f (128x66)
    float* WtF = sm + 8448;     // 64 x 68
    __shared__ float pWs[64];

    const int tid = threadIdx.x;
    const int r0  = blockIdx.x * R1;
    const int tx = tid & 15, ty = tid >> 4;
    const int i0 = ty*8, j0 = tx*4;

    if (tid < 64) pWs[tid] = pW[tid];

    float4 acc[8];
#pragma unroll
    for (int u = 0; u < 8; u++) acc[u] = make_float4(0,0,0,0);

    const float4* rd4 = reinterpret_cast<const float4*>(g_read);
    const float4* kg4 = reinterpret_cast<const float4*>(g_k);

    for (int h = 0; h < 2; h++) {
        if (h) __syncthreads();
        const float4* src = (h == 0) ? rd4 : kg4;
        for (int idx = tid; idx < 2048; idx += 256) {
            int i = idx & 127, c4 = idx >> 7;
            float4 v = src[(size_t)(r0+i)*16 + c4];
            int cb = c4*4;
            inT[(cb+0)*132+i] = v.x; inT[(cb+1)*132+i] = v.y;
            inT[(cb+2)*132+i] = v.z; inT[(cb+3)*132+i] = v.w;
        }
        for (int idx = tid; idx < 4096; idx += 256) {
            int cc = idx & 63, j = idx >> 6;
            WtF[cc*68 + j] = fW[j*128 + h*64 + cc];
        }
        __syncthreads();
#pragma unroll 4
        for (int c = 0; c < 64; c++) {
            float4 x0 = *reinterpret_cast<float4*>(&inT[c*132 + i0]);
            float4 x1 = *reinterpret_cast<float4*>(&inT[c*132 + i0 + 4]);
            float4 w  = *reinterpret_cast<float4*>(&WtF[c*68 + j0]);
            float xs[8] = {x0.x,x0.y,x0.z,x0.w,x1.x,x1.y,x1.z,x1.w};
            fma8x4(xs, w, acc);
        }
    }
    float4 b4 = *reinterpret_cast<const float4*>(&fb[j0]);
    __syncthreads();

    float* fS = inT;
#pragma unroll
    for (int u = 0; u < 8; u++) {
        int base = (i0+u)*66 + j0;
        fS[base+0] = ftanh_(acc[u].x + b4.x);
        fS[base+1] = ftanh_(acc[u].y + b4.y);
        fS[base+2] = ftanh_(acc[u].z + b4.z);
        fS[base+3] = ftanh_(acc[u].w + b4.w);
    }
    __syncthreads();

    if (tid < R1) {
        float s = pb[0];
        for (int j = 0; j < 64; j++) s = fmaf(pWs[j], fS[tid*66 + j], s);
        out[r0 + tid] = fsig(s);
    }
}

// ---------------------------------------------------------------------------
extern "C" void kernel_launch(void* const* d_in, const int* in_sizes, int n_in,
                              void* d_out, int out_size)
{
    const int*   q     = (const int*)  d_in[0];
    const int*   r     = (const int*)  d_in[1];
    const float* k_emb = (const float*)d_in[2];
    const float* v_emb = (const float*)d_in[3];
    const float* Mk    = (const float*)d_in[4];
    const float* Mv0   = (const float*)d_in[5];
    const float* eW    = (const float*)d_in[6];
    const float* eb    = (const float*)d_in[7];
    const float* aW    = (const float*)d_in[8];
    const float* ab    = (const float*)d_in[9];
    const float* fW    = (const float*)d_in[10];
    const float* fb    = (const float*)d_in[11];
    const float* pW    = (const float*)d_in[12];
    const float* pb    = (const float*)d_in[13];
    float* out = (float*)d_out;

    const int SMEM1 = 17152 * 4;             // 68608 B (dual weight buffers)
    const int SMEM3 = (8448 + 4352) * 4;     // 51200 B
    cudaFuncSetAttribute(k1_heads, cudaFuncAttributeMaxDynamicSharedMemorySize, SMEM1);
    cudaFuncSetAttribute(k3_out,   cudaFuncAttributeMaxDynamicSharedMemorySize, SMEM3);

    k1_heads<<<NC1, 256, SMEM1>>>(q, r, k_emb, v_emb, Mk, eW, eb, aW, ab);
    k2_scan <<<BATCH, 320>>>(Mv0, out);
    k3_out  <<<NC1, 256, SMEM3>>>(fW, fb, pW, pb, out);
}